// round 4
// baseline (speedup 1.0000x reference)
#include <cuda_runtime.h>
#include <math.h>

#define BN 8192
#define DD 512
#define MARGIN 0.3f
#define NB 64               // 8192 / 128 block tiles per dim
#define INF_BITS 0x7F800000

// -------- device scratch (no allocations allowed) --------
__device__ float g_fn[(size_t)BN * DD];   // normalized features (16 MB)
__device__ float g_sq[BN];                // ||f_i||^2 after normalize
__device__ int   g_lab[BN];               // labels as int32
__device__ float g_mean[BN];              // mean positive distance per anchor
__device__ int   g_pcnt[BN];              // positive count (incl. self)
__device__ int   g_minsh[BN];             // min semi-hard dist, float bits (>=0)
__device__ float g_rowval[BN];            // per-anchor loss contribution
__device__ int   g_rowcnt[BN];            // per-anchor contrib flag

// ---------------- labels int64 -> int32 ----------------
__global__ void k_labels(const long long* __restrict__ lab) {
    int i = blockIdx.x * blockDim.x + threadIdx.x;
    if (i < BN) g_lab[i] = (int)lab[i];
}

// ---------------- init min array ----------------
__global__ void k_init() {
    int i = blockIdx.x * blockDim.x + threadIdx.x;
    if (i < BN) g_minsh[i] = INF_BITS;
}

// ---------------- row L2 normalize ----------------
__global__ void k_norm(const float* __restrict__ X) {
    int row = blockIdx.x;
    int t = threadIdx.x;
    const float4* xr = (const float4*)(X + (size_t)row * DD);
    float4 v = xr[t];
    float ss = v.x * v.x + v.y * v.y + v.z * v.z + v.w * v.w;
    #pragma unroll
    for (int off = 16; off > 0; off >>= 1)
        ss += __shfl_xor_sync(0xffffffffu, ss, off);
    __shared__ float ws[4];
    if ((t & 31) == 0) ws[t >> 5] = ss;
    __syncthreads();
    float tot = ws[0] + ws[1] + ws[2] + ws[3];
    float den = fmaxf(sqrtf(tot), 1e-12f);
    float s = 1.0f / den;
    v.x *= s; v.y *= s; v.z *= s; v.w *= s;
    ((float4*)(g_fn + (size_t)row * DD))[t] = v;
    if (t == 0) g_sq[row] = tot * s * s;
}

// ---------------- mean positive distance per anchor ----------------
// one block (256 thr = 8 warps) per anchor. Warp w scans j = w, w+8, ...
// Positives are ~64/row so the dot-product work is tiny. Deterministic:
// fixed warp partition, warp sums combined in fixed ascending order.
__global__ __launch_bounds__(256) void k_meanpos() {
    int i = blockIdx.x;
    int tid = threadIdx.x;
    int w = tid >> 5;
    int lane = tid & 31;

    __shared__ float fi[DD];
    #pragma unroll
    for (int k = tid; k < DD; k += 256) fi[k] = g_fn[(size_t)i * DD + k];
    __shared__ float wsum[8];
    __shared__ int   wcnt[8];
    int li = g_lab[i];
    float sqi = g_sq[i];
    __syncthreads();

    float psum = 0.0f;
    int   pcnt = 0;
    for (int j = w; j < BN; j += 8) {
        int lj = g_lab[j];                 // warp-uniform
        if (lj == li) {
            const float* fj = g_fn + (size_t)j * DD;
            float dot = 0.0f;
            #pragma unroll
            for (int k = lane; k < DD; k += 32)
                dot = fmaf(fi[k], fj[k], dot);
            #pragma unroll
            for (int off = 16; off > 0; off >>= 1)
                dot += __shfl_xor_sync(0xffffffffu, dot, off);
            float d2 = sqi + g_sq[j] - 2.0f * dot;
            float d = (j == i) ? 0.0f : sqrtf(fmaxf(d2, 0.0f));
            psum += d;
            pcnt += 1;
        }
    }
    if (lane == 0) { wsum[w] = psum; wcnt[w] = pcnt; }
    __syncthreads();
    if (tid == 0) {
        float ts = 0.0f; int tc = 0;
        #pragma unroll
        for (int q = 0; q < 8; q++) { ts += wsum[q]; tc += wcnt[q]; }
        g_pcnt[i] = tc;
        g_mean[i] = ts / (float)tc;        // tc >= 1 (self)
    }
}

// ---------------- fused symmetric distance GEMM + semi-hard min ----------------
// Upper-triangle tiles only (bi <= bj). 128x128 tile, BK=8, 256 thr, 8x8/thread.
// Epilogue: min over semi-hard negatives for both row-range and col-range.
__global__ __launch_bounds__(256) void k_fused() {
    __shared__ float As[8][132];
    __shared__ float Bs[8][132];
    __shared__ int   s_rlab[128], s_clab[128];
    __shared__ float s_rmean[128], s_cmean[128];
    __shared__ int   s_cmin[128];

    // linear block -> upper-triangle (bi, bj)
    int rem = blockIdx.x, bi = 0, len = NB;
    while (rem >= len) { rem -= len; len--; bi++; }
    int bj = bi + rem;

    int tid  = threadIdx.x;
    int row0 = bi * 128;
    int col0 = bj * 128;

    if (tid < 128) {
        s_rlab[tid]  = g_lab[row0 + tid];
        s_clab[tid]  = g_lab[col0 + tid];
        s_rmean[tid] = g_mean[row0 + tid];
        s_cmean[tid] = g_mean[col0 + tid];
        s_cmin[tid]  = INF_BITS;
    }

    float acc[8][8];
    #pragma unroll
    for (int r = 0; r < 8; r++)
        #pragma unroll
        for (int c = 0; c < 8; c++) acc[r][c] = 0.0f;

    int lr = tid >> 1;
    int lk = (tid & 1) * 4;
    const float* Aptr = g_fn + (size_t)(row0 + lr) * DD + lk;
    const float* Bptr = g_fn + (size_t)(col0 + lr) * DD + lk;

    int tx = tid & 15;
    int ty = tid >> 4;

    for (int kt = 0; kt < DD; kt += 8) {
        float4 va = *(const float4*)(Aptr + kt);
        float4 vb = *(const float4*)(Bptr + kt);
        __syncthreads();
        As[lk + 0][lr] = va.x; As[lk + 1][lr] = va.y;
        As[lk + 2][lr] = va.z; As[lk + 3][lr] = va.w;
        Bs[lk + 0][lr] = vb.x; Bs[lk + 1][lr] = vb.y;
        Bs[lk + 2][lr] = vb.z; Bs[lk + 3][lr] = vb.w;
        __syncthreads();

        #pragma unroll
        for (int kk = 0; kk < 8; kk++) {
            float ar[8], br[8];
            *(float4*)(ar)     = *(const float4*)&As[kk][ty * 8];
            *(float4*)(ar + 4) = *(const float4*)&As[kk][ty * 8 + 4];
            *(float4*)(br)     = *(const float4*)&Bs[kk][tx * 8];
            *(float4*)(br + 4) = *(const float4*)&Bs[kk][tx * 8 + 4];
            #pragma unroll
            for (int r = 0; r < 8; r++)
                #pragma unroll
                for (int c = 0; c < 8; c++)
                    acc[r][c] = fmaf(ar[r], br[c], acc[r][c]);
        }
    }

    // ---- epilogue: distances + semi-hard min (both orientations) ----
    float sqa[8], sqb[8], rm[8], cm[8];
    int rl[8], cl[8];
    #pragma unroll
    for (int r = 0; r < 8; r++) {
        int rr = ty * 8 + r;
        sqa[r] = g_sq[row0 + rr];
        rl[r]  = s_rlab[rr];
        rm[r]  = s_rmean[rr];
    }
    #pragma unroll
    for (int c = 0; c < 8; c++) {
        int cc = tx * 8 + c;
        sqb[c] = g_sq[col0 + cc];
        cl[c]  = s_clab[cc];
        cm[c]  = s_cmean[cc];
    }

    float rowmin[8], colmin[8];
    #pragma unroll
    for (int r = 0; r < 8; r++) rowmin[r] = __int_as_float(INF_BITS);
    #pragma unroll
    for (int c = 0; c < 8; c++) colmin[c] = __int_as_float(INF_BITS);

    #pragma unroll
    for (int r = 0; r < 8; r++) {
        #pragma unroll
        for (int c = 0; c < 8; c++) {
            float d2 = sqa[r] + sqb[c] - 2.0f * acc[r][c];
            float d = sqrtf(fmaxf(d2, 0.0f));
            if (rl[r] != cl[c]) {
                if (d > rm[r]) rowmin[r] = fminf(rowmin[r], d);
                if (d > cm[c]) colmin[c] = fminf(colmin[c], d);
            }
        }
    }

    // row minima: threads sharing ty are the 16 tx lanes of one warp half
    #pragma unroll
    for (int r = 0; r < 8; r++) {
        float v = rowmin[r];
        #pragma unroll
        for (int off = 8; off > 0; off >>= 1)
            v = fminf(v, __shfl_xor_sync(0xffffffffu, v, off));
        if (tx == 0) {
            int b = __float_as_int(v);
            if (b != INF_BITS) atomicMin(&g_minsh[row0 + ty * 8 + r], b);
        }
    }

    // col minima: fold the two ty values inside the warp, then smem atomics
    #pragma unroll
    for (int c = 0; c < 8; c++) {
        float v = colmin[c];
        v = fminf(v, __shfl_xor_sync(0xffffffffu, v, 16));
        if ((tid & 31) < 16) {
            int b = __float_as_int(v);
            if (b != INF_BITS) atomicMin(&s_cmin[tx * 8 + c], b);
        }
    }
    __syncthreads();
    if (tid < 128) {
        int b = s_cmin[tid];
        if (b != INF_BITS) atomicMin(&g_minsh[col0 + tid], b);
    }
}

// ---------------- deterministic final reduction ----------------
__global__ void k_final(float* __restrict__ out) {
    int t = threadIdx.x;   // 256
    float s = 0.0f;
    int   c = 0;
    for (int j = t; j < BN; j += 256) {
        int pc = g_pcnt[j];
        int mb = g_minsh[j];
        bool valid  = (pc > 1) && (pc < BN);
        bool has_sh = (mb != INF_BITS);
        if (valid && has_sh) {
            float per = fmaxf(g_mean[j] - __int_as_float(mb) + MARGIN, 0.0f);
            s += per;
            c += 1;
        }
    }
    #pragma unroll
    for (int off = 16; off > 0; off >>= 1) {
        s += __shfl_xor_sync(0xffffffffu, s, off);
        c += __shfl_xor_sync(0xffffffffu, c, off);
    }
    __shared__ float ws[8];
    __shared__ int   wc[8];
    int warp = t >> 5;
    if ((t & 31) == 0) { ws[warp] = s; wc[warp] = c; }
    __syncthreads();
    if (t == 0) {
        float ts = 0.0f; int tc = 0;
        #pragma unroll
        for (int w = 0; w < 8; w++) { ts += ws[w]; tc += wc[w]; }
        out[0] = (tc > 0) ? ts / (float)tc : 0.0f;
    }
}

extern "C" void kernel_launch(void* const* d_in, const int* in_sizes, int n_in,
                              void* d_out, int out_size) {
    const float*     X   = (const float*)d_in[0];
    const long long* lab = (const long long*)d_in[1];
    float*           out = (float*)d_out;

    k_labels<<<(BN + 255) / 256, 256>>>(lab);
    k_init<<<(BN + 255) / 256, 256>>>();
    k_norm<<<BN, 128>>>(X);
    k_meanpos<<<BN, 256>>>();
    int ntiles = NB * (NB + 1) / 2;   // 2080 upper-triangle tiles
    k_fused<<<ntiles, 256>>>();
    k_final<<<1, 256>>>(out);
}

// round 5
// speedup vs baseline: 1.0015x; 1.0015x over previous
#include <cuda_runtime.h>
#include <math.h>

#define BN 8192
#define DD 512
#define MARGIN 0.3f
#define NB 64               // 8192 / 128 block tiles per dim
#define INF_BITS 0x7F800000

// -------- device scratch (no allocations allowed) --------
__device__ float g_fn[(size_t)BN * DD];   // normalized features (16 MB)
__device__ float g_sq[BN];                // ||f_i||^2 after normalize
__device__ int   g_lab[BN];               // labels as int32
__device__ float g_mean[BN];              // mean positive distance per anchor
__device__ int   g_pcnt[BN];              // positive count (incl. self)
__device__ int   g_minsh[BN];             // min semi-hard dist, float bits (>=0)

// ---------------- labels int64 -> int32 ----------------
__global__ void k_labels(const long long* __restrict__ lab) {
    int i = blockIdx.x * blockDim.x + threadIdx.x;
    if (i < BN) g_lab[i] = (int)lab[i];
}

// ---------------- init min array ----------------
__global__ void k_init() {
    int i = blockIdx.x * blockDim.x + threadIdx.x;
    if (i < BN) g_minsh[i] = INF_BITS;
}

// ---------------- row L2 normalize ----------------
__global__ void k_norm(const float* __restrict__ X) {
    int row = blockIdx.x;
    int t = threadIdx.x;
    const float4* xr = (const float4*)(X + (size_t)row * DD);
    float4 v = xr[t];
    float ss = v.x * v.x + v.y * v.y + v.z * v.z + v.w * v.w;
    #pragma unroll
    for (int off = 16; off > 0; off >>= 1)
        ss += __shfl_xor_sync(0xffffffffu, ss, off);
    __shared__ float ws[4];
    if ((t & 31) == 0) ws[t >> 5] = ss;
    __syncthreads();
    float tot = ws[0] + ws[1] + ws[2] + ws[3];
    float den = fmaxf(sqrtf(tot), 1e-12f);
    float s = 1.0f / den;
    v.x *= s; v.y *= s; v.z *= s; v.w *= s;
    ((float4*)(g_fn + (size_t)row * DD))[t] = v;
    if (t == 0) g_sq[row] = tot * s * s;
}

// ---------------- mean positive distance per anchor ----------------
__global__ __launch_bounds__(256) void k_meanpos() {
    int i = blockIdx.x;
    int tid = threadIdx.x;
    int w = tid >> 5;
    int lane = tid & 31;

    __shared__ float fi[DD];
    #pragma unroll
    for (int k = tid; k < DD; k += 256) fi[k] = g_fn[(size_t)i * DD + k];
    __shared__ float wsum[8];
    __shared__ int   wcnt[8];
    int li = g_lab[i];
    float sqi = g_sq[i];
    __syncthreads();

    float psum = 0.0f;
    int   pcnt = 0;
    for (int j = w; j < BN; j += 8) {
        int lj = g_lab[j];                 // warp-uniform
        if (lj == li) {
            const float* fj = g_fn + (size_t)j * DD;
            float dot = 0.0f;
            #pragma unroll
            for (int k = lane; k < DD; k += 32)
                dot = fmaf(fi[k], fj[k], dot);
            #pragma unroll
            for (int off = 16; off > 0; off >>= 1)
                dot += __shfl_xor_sync(0xffffffffu, dot, off);
            float d2 = sqi + g_sq[j] - 2.0f * dot;
            float d = (j == i) ? 0.0f : sqrtf(fmaxf(d2, 0.0f));
            psum += d;
            pcnt += 1;
        }
    }
    if (lane == 0) { wsum[w] = psum; wcnt[w] = pcnt; }
    __syncthreads();
    if (tid == 0) {
        float ts = 0.0f; int tc = 0;
        #pragma unroll
        for (int q = 0; q < 8; q++) { ts += wsum[q]; tc += wcnt[q]; }
        g_pcnt[i] = tc;
        g_mean[i] = ts / (float)tc;        // tc >= 1 (self)
    }
}

// ---------------- fused symmetric distance GEMM + semi-hard min ----------------
// Upper-triangle tiles only. 128x128 tile, BK=8, 256 thr, 8x8/thread.
// __launch_bounds__(256, 2): cap at 128 regs so 2 CTAs/SM stay resident —
// the R4 regression was epilogue register pressure dropping to 1 CTA/SM.
__global__ __launch_bounds__(256, 2) void k_fused() {
    __shared__ float As[8][132];
    __shared__ float Bs[8][132];
    __shared__ int   s_rlab[128], s_clab[128];
    __shared__ float s_rmean[128], s_cmean[128];
    __shared__ float s_rsq[128], s_csq[128];
    __shared__ int   s_cmin[128];

    // linear block -> upper-triangle (bi, bj)
    int rem = blockIdx.x, bi = 0, len = NB;
    while (rem >= len) { rem -= len; len--; bi++; }
    int bj = bi + rem;

    int tid  = threadIdx.x;
    int row0 = bi * 128;
    int col0 = bj * 128;

    if (tid < 128) {
        s_rlab[tid]  = g_lab[row0 + tid];
        s_clab[tid]  = g_lab[col0 + tid];
        s_rmean[tid] = g_mean[row0 + tid];
        s_cmean[tid] = g_mean[col0 + tid];
        s_rsq[tid]   = g_sq[row0 + tid];
        s_csq[tid]   = g_sq[col0 + tid];
        s_cmin[tid]  = INF_BITS;
    }

    float acc[8][8];
    #pragma unroll
    for (int r = 0; r < 8; r++)
        #pragma unroll
        for (int c = 0; c < 8; c++) acc[r][c] = 0.0f;

    int lr = tid >> 1;
    int lk = (tid & 1) * 4;
    const float* Aptr = g_fn + (size_t)(row0 + lr) * DD + lk;
    const float* Bptr = g_fn + (size_t)(col0 + lr) * DD + lk;

    int tx = tid & 15;
    int ty = tid >> 4;

    for (int kt = 0; kt < DD; kt += 8) {
        float4 va = *(const float4*)(Aptr + kt);
        float4 vb = *(const float4*)(Bptr + kt);
        __syncthreads();
        As[lk + 0][lr] = va.x; As[lk + 1][lr] = va.y;
        As[lk + 2][lr] = va.z; As[lk + 3][lr] = va.w;
        Bs[lk + 0][lr] = vb.x; Bs[lk + 1][lr] = vb.y;
        Bs[lk + 2][lr] = vb.z; Bs[lk + 3][lr] = vb.w;
        __syncthreads();

        #pragma unroll
        for (int kk = 0; kk < 8; kk++) {
            float ar[8], br[8];
            *(float4*)(ar)     = *(const float4*)&As[kk][ty * 8];
            *(float4*)(ar + 4) = *(const float4*)&As[kk][ty * 8 + 4];
            *(float4*)(br)     = *(const float4*)&Bs[kk][tx * 8];
            *(float4*)(br + 4) = *(const float4*)&Bs[kk][tx * 8 + 4];
            #pragma unroll
            for (int r = 0; r < 8; r++)
                #pragma unroll
                for (int c = 0; c < 8; c++)
                    acc[r][c] = fmaf(ar[r], br[c], acc[r][c]);
        }
    }

    // ---- epilogue: row-at-a-time to keep live registers low ----
    float sqb[8], cm[8];
    int cl[8];
    #pragma unroll
    for (int c = 0; c < 8; c++) {
        int cc = tx * 8 + c;
        sqb[c] = s_csq[cc];
        cl[c]  = s_clab[cc];
        cm[c]  = s_cmean[cc];
    }
    float colmin[8];
    #pragma unroll
    for (int c = 0; c < 8; c++) colmin[c] = __int_as_float(INF_BITS);

    #pragma unroll
    for (int r = 0; r < 8; r++) {
        int rr = ty * 8 + r;
        float sqa = s_rsq[rr];
        int   rl  = s_rlab[rr];
        float rm  = s_rmean[rr];
        float rmin = __int_as_float(INF_BITS);
        #pragma unroll
        for (int c = 0; c < 8; c++) {
            float d2 = sqa + sqb[c] - 2.0f * acc[r][c];
            float d = sqrtf(fmaxf(d2, 0.0f));
            if (rl != cl[c]) {
                if (d > rm)    rmin      = fminf(rmin, d);
                if (d > cm[c]) colmin[c] = fminf(colmin[c], d);
            }
        }
        // reduce rmin over the 16 tx lanes (same ty -> consecutive half-warp)
        #pragma unroll
        for (int off = 8; off > 0; off >>= 1)
            rmin = fminf(rmin, __shfl_xor_sync(0xffffffffu, rmin, off));
        if (tx == 0) {
            int b = __float_as_int(rmin);
            if (b != INF_BITS) atomicMin(&g_minsh[row0 + rr], b);
        }
    }

    // col minima: fold the two ty halves inside the warp, then smem atomics
    #pragma unroll
    for (int c = 0; c < 8; c++) {
        float v = colmin[c];
        v = fminf(v, __shfl_xor_sync(0xffffffffu, v, 16));
        if ((tid & 31) < 16) {
            int b = __float_as_int(v);
            if (b != INF_BITS) atomicMin(&s_cmin[tx * 8 + c], b);
        }
    }
    __syncthreads();
    if (tid < 128) {
        int b = s_cmin[tid];
        if (b != INF_BITS) atomicMin(&g_minsh[col0 + tid], b);
    }
}

// ---------------- deterministic final reduction ----------------
__global__ void k_final(float* __restrict__ out) {
    int t = threadIdx.x;   // 256
    float s = 0.0f;
    int   c = 0;
    for (int j = t; j < BN; j += 256) {
        int pc = g_pcnt[j];
        int mb = g_minsh[j];
        bool valid  = (pc > 1) && (pc < BN);
        bool has_sh = (mb != INF_BITS);
        if (valid && has_sh) {
            float per = fmaxf(g_mean[j] - __int_as_float(mb) + MARGIN, 0.0f);
            s += per;
            c += 1;
        }
    }
    #pragma unroll
    for (int off = 16; off > 0; off >>= 1) {
        s += __shfl_xor_sync(0xffffffffu, s, off);
        c += __shfl_xor_sync(0xffffffffu, c, off);
    }
    __shared__ float ws[8];
    __shared__ int   wc[8];
    int warp = t >> 5;
    if ((t & 31) == 0) { ws[warp] = s; wc[warp] = c; }
    __syncthreads();
    if (t == 0) {
        float ts = 0.0f; int tc = 0;
        #pragma unroll
        for (int w = 0; w < 8; w++) { ts += ws[w]; tc += wc[w]; }
        out[0] = (tc > 0) ? ts / (float)tc : 0.0f;
    }
}

extern "C" void kernel_launch(void* const* d_in, const int* in_sizes, int n_in,
                              void* d_out, int out_size) {
    const float*     X   = (const float*)d_in[0];
    const long long* lab = (const long long*)d_in[1];
    float*           out = (float*)d_out;

    k_labels<<<(BN + 255) / 256, 256>>>(lab);
    k_init<<<(BN + 255) / 256, 256>>>();
    k_norm<<<BN, 128>>>(X);
    k_meanpos<<<BN, 256>>>();
    int ntiles = NB * (NB + 1) / 2;   // 2080 upper-triangle tiles
    k_fused<<<ntiles, 256>>>();
    k_final<<<1, 256>>>(out);
}

// round 7
// speedup vs baseline: 4.2311x; 4.2245x over previous
#include <cuda_runtime.h>
#include <math.h>

#define BN 8192
#define DD 512
#define MARGIN 0.3f

// -------- device scratch (no allocations allowed) --------
__device__ float g_fn[(size_t)BN * DD];        // normalized features (16 MB)
__device__ float g_sq[BN];                     // ||f_i||^2 after normalize
__device__ int   g_lab[BN];                    // labels as int32
__device__ float g_dist[(size_t)BN * BN];      // pairwise distances (256 MB)
__device__ float g_rowval[BN];                 // per-anchor loss contribution
__device__ int   g_rowcnt[BN];                 // per-anchor contrib flag

// ---------------- labels int64 -> int32 ----------------
__global__ void k_labels(const long long* __restrict__ lab) {
    int i = blockIdx.x * blockDim.x + threadIdx.x;
    if (i < BN) g_lab[i] = (int)lab[i];
}

// ---------------- row L2 normalize ----------------
__global__ void k_norm(const float* __restrict__ X) {
    int row = blockIdx.x;
    int t = threadIdx.x;
    const float4* xr = (const float4*)(X + (size_t)row * DD);
    float4 v = xr[t];
    float ss = v.x * v.x + v.y * v.y + v.z * v.z + v.w * v.w;
    #pragma unroll
    for (int off = 16; off > 0; off >>= 1)
        ss += __shfl_xor_sync(0xffffffffu, ss, off);
    __shared__ float ws[4];
    if ((t & 31) == 0) ws[t >> 5] = ss;
    __syncthreads();
    float tot = ws[0] + ws[1] + ws[2] + ws[3];
    float den = fmaxf(sqrtf(tot), 1e-12f);
    float s = 1.0f / den;
    v.x *= s; v.y *= s; v.z *= s; v.w *= s;
    ((float4*)(g_fn + (size_t)row * DD))[t] = v;
    if (t == 0) g_sq[row] = tot * s * s;
}

// ---------------- symmetric pairwise distance GEMM ----------------
// Upper-triangle tiles only (bi <= bj); each computed tile is stored twice:
// direct at [rows, cols] and transposed at [cols, rows]. Mainloop is byte-
// identical to the proven R2 k_gemm. 128x128 tile, BK=8, 256 thr, 8x8/thread.
__global__ __launch_bounds__(256) void k_gemm() {
    int bi = blockIdx.y;     // row tile
    int bj = blockIdx.x;     // col tile
    if (bj < bi) return;     // lower triangle handled by transposed store

    __shared__ float As[8][132];
    __shared__ float Bs[8][132];

    int tid  = threadIdx.x;
    int row0 = bi * 128;
    int col0 = bj * 128;

    float acc[8][8];
    #pragma unroll
    for (int r = 0; r < 8; r++)
        #pragma unroll
        for (int c = 0; c < 8; c++) acc[r][c] = 0.0f;

    int lr = tid >> 1;          // 0..127 : row within tile for loading
    int lk = (tid & 1) * 4;     // 0 or 4 : k offset for loading

    const float* Aptr = g_fn + (size_t)(row0 + lr) * DD + lk;
    const float* Bptr = g_fn + (size_t)(col0 + lr) * DD + lk;

    int tx = tid & 15;          // 0..15 column group
    int ty = tid >> 4;          // 0..15 row group

    for (int kt = 0; kt < DD; kt += 8) {
        float4 va = *(const float4*)(Aptr + kt);
        float4 vb = *(const float4*)(Bptr + kt);
        __syncthreads();
        As[lk + 0][lr] = va.x; As[lk + 1][lr] = va.y;
        As[lk + 2][lr] = va.z; As[lk + 3][lr] = va.w;
        Bs[lk + 0][lr] = vb.x; Bs[lk + 1][lr] = vb.y;
        Bs[lk + 2][lr] = vb.z; Bs[lk + 3][lr] = vb.w;
        __syncthreads();

        #pragma unroll
        for (int kk = 0; kk < 8; kk++) {
            float ar[8], br[8];
            *(float4*)(ar)     = *(const float4*)&As[kk][ty * 8];
            *(float4*)(ar + 4) = *(const float4*)&As[kk][ty * 8 + 4];
            *(float4*)(br)     = *(const float4*)&Bs[kk][tx * 8];
            *(float4*)(br + 4) = *(const float4*)&Bs[kk][tx * 8 + 4];
            #pragma unroll
            for (int r = 0; r < 8; r++)
                #pragma unroll
                for (int c = 0; c < 8; c++)
                    acc[r][c] = fmaf(ar[r], br[c], acc[r][c]);
        }
    }

    // ---- epilogue: convert acc -> distance in place (no extra registers) ----
    float sqa[8], sqb[8];
    #pragma unroll
    for (int r = 0; r < 8; r++) sqa[r] = g_sq[row0 + ty * 8 + r];
    #pragma unroll
    for (int c = 0; c < 8; c++) sqb[c] = g_sq[col0 + tx * 8 + c];

    #pragma unroll
    for (int r = 0; r < 8; r++)
        #pragma unroll
        for (int c = 0; c < 8; c++) {
            float d2 = sqa[r] + sqb[c] - 2.0f * acc[r][c];
            acc[r][c] = sqrtf(fmaxf(d2, 0.0f));
        }

    // direct store: rows [row0 + ty*8 .. +7], cols [col0 + tx*8 .. +7]
    #pragma unroll
    for (int r = 0; r < 8; r++) {
        float* dst = g_dist + (size_t)(row0 + ty * 8 + r) * BN + col0 + tx * 8;
        *(float4*)(dst)     = make_float4(acc[r][0], acc[r][1], acc[r][2], acc[r][3]);
        *(float4*)(dst + 4) = make_float4(acc[r][4], acc[r][5], acc[r][6], acc[r][7]);
    }

    // transposed store: rows [col0 + tx*8 .. +7], cols [row0 + ty*8 .. +7]
    // (each lane writes two 16B chunks; lane pairs form full 32B sectors)
    #pragma unroll
    for (int c = 0; c < 8; c++) {
        float* dst = g_dist + (size_t)(col0 + tx * 8 + c) * BN + row0 + ty * 8;
        *(float4*)(dst)     = make_float4(acc[0][c], acc[1][c], acc[2][c], acc[3][c]);
        *(float4*)(dst + 4) = make_float4(acc[4][c], acc[5][c], acc[6][c], acc[7][c]);
    }
}

// ---------------- per-anchor semi-hard stats ----------------
// one block (256 threads) per anchor row; each thread handles 32 columns.
__global__ __launch_bounds__(256) void k_stats() {
    int i = blockIdx.x;
    int tid = threadIdx.x;
    const float* drow = g_dist + (size_t)i * BN;
    int li = g_lab[i];

    float d[32];
    unsigned match = 0;
    float psum = 0.0f;
    int   pcnt = 0;

    #pragma unroll
    for (int c = 0; c < 32; c++) {
        int j = tid + (c << 8);
        float dv = (j == i) ? 0.0f : drow[j];    // force exact-zero diagonal
        d[c] = dv;
        int lj = g_lab[j];
        if (lj == li) {
            match |= (1u << c);
            psum += dv;
            pcnt += 1;
        }
    }

    #pragma unroll
    for (int off = 16; off > 0; off >>= 1) {
        psum += __shfl_xor_sync(0xffffffffu, psum, off);
        pcnt += __shfl_xor_sync(0xffffffffu, pcnt, off);
    }
    __shared__ float ws[8];
    __shared__ int   wc[8];
    __shared__ float s_mean;
    __shared__ int   s_pcnt;
    int warp = tid >> 5;
    if ((tid & 31) == 0) { ws[warp] = psum; wc[warp] = pcnt; }
    __syncthreads();
    if (tid == 0) {
        float ts = 0.0f; int tc = 0;
        #pragma unroll
        for (int w = 0; w < 8; w++) { ts += ws[w]; tc += wc[w]; }
        s_pcnt = tc;
        s_mean = ts / (float)tc;
    }
    __syncthreads();
    float mean = s_mean;
    int   pc   = s_pcnt;

    float mn = 3.4e38f;
    #pragma unroll
    for (int c = 0; c < 32; c++) {
        bool neg = ((match >> c) & 1u) == 0u;
        if (neg && d[c] > mean) mn = fminf(mn, d[c]);
    }
    #pragma unroll
    for (int off = 16; off > 0; off >>= 1)
        mn = fminf(mn, __shfl_xor_sync(0xffffffffu, mn, off));
    if ((tid & 31) == 0) ws[warp] = mn;
    __syncthreads();
    if (tid == 0) {
        float m = 3.4e38f;
        #pragma unroll
        for (int w = 0; w < 8; w++) m = fminf(m, ws[w]);
        bool valid  = (pc > 1) && (pc < BN);
        bool has_sh = (m < 1e37f);
        bool contrib = valid && has_sh;
        float per = fmaxf(mean - m + MARGIN, 0.0f);
        g_rowval[i] = contrib ? per : 0.0f;
        g_rowcnt[i] = contrib ? 1 : 0;
    }
}

// ---------------- deterministic final reduction ----------------
__global__ void k_final(float* __restrict__ out) {
    int t = threadIdx.x;   // 256
    float s = 0.0f;
    int   c = 0;
    for (int j = t; j < BN; j += 256) { s += g_rowval[j]; c += g_rowcnt[j]; }
    #pragma unroll
    for (int off = 16; off > 0; off >>= 1) {
        s += __shfl_xor_sync(0xffffffffu, s, off);
        c += __shfl_xor_sync(0xffffffffu, c, off);
    }
    __shared__ float ws[8];
    __shared__ int   wc[8];
    int warp = t >> 5;
    if ((t & 31) == 0) { ws[warp] = s; wc[warp] = c; }
    __syncthreads();
    if (t == 0) {
        float ts = 0.0f; int tc = 0;
        #pragma unroll
        for (int w = 0; w < 8; w++) { ts += ws[w]; tc += wc[w]; }
        out[0] = (tc > 0) ? ts / (float)tc : 0.0f;
    }
}

extern "C" void kernel_launch(void* const* d_in, const int* in_sizes, int n_in,
                              void* d_out, int out_size) {
    const float*     X   = (const float*)d_in[0];
    const long long* lab = (const long long*)d_in[1];
    float*           out = (float*)d_out;

    k_labels<<<(BN + 255) / 256, 256>>>(lab);
    k_norm<<<BN, 128>>>(X);
    dim3 grid(BN / 128, BN / 128);
    k_gemm<<<grid, 256>>>();
    k_stats<<<BN, 256>>>();
    k_final<<<1, 256>>>(out);
}

// round 9
// speedup vs baseline: 4.5069x; 1.0652x over previous
#include <cuda_runtime.h>
#include <math.h>

#define BN 8192
#define DD 512
#define MARGIN 0.3f

// -------- device scratch (no allocations allowed) --------
__device__ float g_fn[(size_t)BN * DD];        // normalized features (16 MB)
__device__ float g_sq[BN];                     // ||f_i||^2 after normalize
__device__ int   g_lab[BN];                    // labels as int32
__device__ float g_dist[(size_t)BN * BN];      // pairwise distances (256 MB)
__device__ float g_rowval[BN];                 // per-anchor loss contribution
__device__ int   g_rowcnt[BN];                 // per-anchor contrib flag

// ---------------- labels int64 -> int32 ----------------
__global__ void k_labels(const long long* __restrict__ lab) {
    int i = blockIdx.x * blockDim.x + threadIdx.x;
    if (i < BN) g_lab[i] = (int)lab[i];
}

// ---------------- row L2 normalize ----------------
__global__ void k_norm(const float* __restrict__ X) {
    int row = blockIdx.x;
    int t = threadIdx.x;
    const float4* xr = (const float4*)(X + (size_t)row * DD);
    float4 v = xr[t];
    float ss = v.x * v.x + v.y * v.y + v.z * v.z + v.w * v.w;
    #pragma unroll
    for (int off = 16; off > 0; off >>= 1)
        ss += __shfl_xor_sync(0xffffffffu, ss, off);
    __shared__ float ws[4];
    if ((t & 31) == 0) ws[t >> 5] = ss;
    __syncthreads();
    float tot = ws[0] + ws[1] + ws[2] + ws[3];
    float den = fmaxf(sqrtf(tot), 1e-12f);
    float s = 1.0f / den;
    v.x *= s; v.y *= s; v.z *= s; v.w *= s;
    ((float4*)(g_fn + (size_t)row * DD))[t] = v;
    if (t == 0) g_sq[row] = tot * s * s;
}

// ---------------- symmetric pairwise distance GEMM ----------------
// Upper-triangle tiles only (bi <= bj); each computed tile stored twice
// (direct + transposed from registers). Double-buffered smem mainloop:
// one __syncthreads per BK=8 step, LDG prefetch overlapped with FMA block.
__global__ __launch_bounds__(256) void k_gemm() {
    int bi = blockIdx.y;     // row tile
    int bj = blockIdx.x;     // col tile
    if (bj < bi) return;     // lower triangle handled by transposed store

    __shared__ float As[2][8][132];
    __shared__ float Bs[2][8][132];

    int tid  = threadIdx.x;
    int row0 = bi * 128;
    int col0 = bj * 128;

    float acc[8][8];
    #pragma unroll
    for (int r = 0; r < 8; r++)
        #pragma unroll
        for (int c = 0; c < 8; c++) acc[r][c] = 0.0f;

    int lr = tid >> 1;          // 0..127 : row within tile for loading
    int lk = (tid & 1) * 4;     // 0 or 4 : k offset for loading

    const float* Aptr = g_fn + (size_t)(row0 + lr) * DD + lk;
    const float* Bptr = g_fn + (size_t)(col0 + lr) * DD + lk;

    int tx = tid & 15;          // 0..15 column group
    int ty = tid >> 4;          // 0..15 row group

    // prologue: load k-slice 0 into buffer 0
    {
        float4 va = *(const float4*)(Aptr);
        float4 vb = *(const float4*)(Bptr);
        As[0][lk + 0][lr] = va.x; As[0][lk + 1][lr] = va.y;
        As[0][lk + 2][lr] = va.z; As[0][lk + 3][lr] = va.w;
        Bs[0][lk + 0][lr] = vb.x; Bs[0][lk + 1][lr] = vb.y;
        Bs[0][lk + 2][lr] = vb.z; Bs[0][lk + 3][lr] = vb.w;
    }
    __syncthreads();

    int cur = 0;
    for (int kt = 8; kt < DD; kt += 8) {
        // prefetch next slice (LDG overlaps the FMA block below)
        float4 va = *(const float4*)(Aptr + kt);
        float4 vb = *(const float4*)(Bptr + kt);

        #pragma unroll
        for (int kk = 0; kk < 8; kk++) {
            float ar[8], br[8];
            *(float4*)(ar)     = *(const float4*)&As[cur][kk][ty * 8];
            *(float4*)(ar + 4) = *(const float4*)&As[cur][kk][ty * 8 + 4];
            *(float4*)(br)     = *(const float4*)&Bs[cur][kk][tx * 8];
            *(float4*)(br + 4) = *(const float4*)&Bs[cur][kk][tx * 8 + 4];
            #pragma unroll
            for (int r = 0; r < 8; r++)
                #pragma unroll
                for (int c = 0; c < 8; c++)
                    acc[r][c] = fmaf(ar[r], br[c], acc[r][c]);
        }

        int nxt = cur ^ 1;
        As[nxt][lk + 0][lr] = va.x; As[nxt][lk + 1][lr] = va.y;
        As[nxt][lk + 2][lr] = va.z; As[nxt][lk + 3][lr] = va.w;
        Bs[nxt][lk + 0][lr] = vb.x; Bs[nxt][lk + 1][lr] = vb.y;
        Bs[nxt][lk + 2][lr] = vb.z; Bs[nxt][lk + 3][lr] = vb.w;
        __syncthreads();
        cur = nxt;
    }

    // final slice
    #pragma unroll
    for (int kk = 0; kk < 8; kk++) {
        float ar[8], br[8];
        *(float4*)(ar)     = *(const float4*)&As[cur][kk][ty * 8];
        *(float4*)(ar + 4) = *(const float4*)&As[cur][kk][ty * 8 + 4];
        *(float4*)(br)     = *(const float4*)&Bs[cur][kk][tx * 8];
        *(float4*)(br + 4) = *(const float4*)&Bs[cur][kk][tx * 8 + 4];
        #pragma unroll
        for (int r = 0; r < 8; r++)
            #pragma unroll
            for (int c = 0; c < 8; c++)
                acc[r][c] = fmaf(ar[r], br[c], acc[r][c]);
    }

    // ---- epilogue: convert acc -> distance in place (no extra registers) ----
    float sqa[8], sqb[8];
    #pragma unroll
    for (int r = 0; r < 8; r++) sqa[r] = g_sq[row0 + ty * 8 + r];
    #pragma unroll
    for (int c = 0; c < 8; c++) sqb[c] = g_sq[col0 + tx * 8 + c];

    #pragma unroll
    for (int r = 0; r < 8; r++)
        #pragma unroll
        for (int c = 0; c < 8; c++) {
            float d2 = sqa[r] + sqb[c] - 2.0f * acc[r][c];
            acc[r][c] = sqrtf(fmaxf(d2, 0.0f));
        }

    // direct store: rows [row0 + ty*8 .. +7], cols [col0 + tx*8 .. +7]
    #pragma unroll
    for (int r = 0; r < 8; r++) {
        float* dst = g_dist + (size_t)(row0 + ty * 8 + r) * BN + col0 + tx * 8;
        *(float4*)(dst)     = make_float4(acc[r][0], acc[r][1], acc[r][2], acc[r][3]);
        *(float4*)(dst + 4) = make_float4(acc[r][4], acc[r][5], acc[r][6], acc[r][7]);
    }

    // transposed store: rows [col0 + tx*8 .. +7], cols [row0 + ty*8 .. +7]
    #pragma unroll
    for (int c = 0; c < 8; c++) {
        float* dst = g_dist + (size_t)(col0 + tx * 8 + c) * BN + row0 + ty * 8;
        *(float4*)(dst)     = make_float4(acc[0][c], acc[1][c], acc[2][c], acc[3][c]);
        *(float4*)(dst + 4) = make_float4(acc[4][c], acc[5][c], acc[6][c], acc[7][c]);
    }
}

// ---------------- per-anchor semi-hard stats ----------------
__global__ __launch_bounds__(256) void k_stats() {
    int i = blockIdx.x;
    int tid = threadIdx.x;
    const float* drow = g_dist + (size_t)i * BN;
    int li = g_lab[i];

    float d[32];
    unsigned match = 0;
    float psum = 0.0f;
    int   pcnt = 0;

    #pragma unroll
    for (int c = 0; c < 32; c++) {
        int j = tid + (c << 8);
        float dv = (j == i) ? 0.0f : drow[j];    // force exact-zero diagonal
        d[c] = dv;
        int lj = g_lab[j];
        if (lj == li) {
            match |= (1u << c);
            psum += dv;
            pcnt += 1;
        }
    }

    #pragma unroll
    for (int off = 16; off > 0; off >>= 1) {
        psum += __shfl_xor_sync(0xffffffffu, psum, off);
        pcnt += __shfl_xor_sync(0xffffffffu, pcnt, off);
    }
    __shared__ float ws[8];
    __shared__ int   wc[8];
    __shared__ float s_mean;
    __shared__ int   s_pcnt;
    int warp = tid >> 5;
    if ((tid & 31) == 0) { ws[warp] = psum; wc[warp] = pcnt; }
    __syncthreads();
    if (tid == 0) {
        float ts = 0.0f; int tc = 0;
        #pragma unroll
        for (int w = 0; w < 8; w++) { ts += ws[w]; tc += wc[w]; }
        s_pcnt = tc;
        s_mean = ts / (float)tc;
    }
    __syncthreads();
    float mean = s_mean;
    int   pc   = s_pcnt;

    float mn = 3.4e38f;
    #pragma unroll
    for (int c = 0; c < 32; c++) {
        bool neg = ((match >> c) & 1u) == 0u;
        if (neg && d[c] > mean) mn = fminf(mn, d[c]);
    }
    #pragma unroll
    for (int off = 16; off > 0; off >>= 1)
        mn = fminf(mn, __shfl_xor_sync(0xffffffffu, mn, off));
    if ((tid & 31) == 0) ws[warp] = mn;
    __syncthreads();
    if (tid == 0) {
        float m = 3.4e38f;
        #pragma unroll
        for (int w = 0; w < 8; w++) m = fminf(m, ws[w]);
        bool valid  = (pc > 1) && (pc < BN);
        bool has_sh = (m < 1e37f);
        bool contrib = valid && has_sh;
        float per = fmaxf(mean - m + MARGIN, 0.0f);
        g_rowval[i] = contrib ? per : 0.0f;
        g_rowcnt[i] = contrib ? 1 : 0;
    }
}

// ---------------- deterministic final reduction ----------------
__global__ void k_final(float* __restrict__ out) {
    int t = threadIdx.x;   // 256
    float s = 0.0f;
    int   c = 0;
    for (int j = t; j < BN; j += 256) { s += g_rowval[j]; c += g_rowcnt[j]; }
    #pragma unroll
    for (int off = 16; off > 0; off >>= 1) {
        s += __shfl_xor_sync(0xffffffffu, s, off);
        c += __shfl_xor_sync(0xffffffffu, c, off);
    }
    __shared__ float ws[8];
    __shared__ int   wc[8];
    int warp = t >> 5;
    if ((t & 31) == 0) { ws[warp] = s; wc[warp] = c; }
    __syncthreads();
    if (t == 0) {
        float ts = 0.0f; int tc = 0;
        #pragma unroll
        for (int w = 0; w < 8; w++) { ts += ws[w]; tc += wc[w]; }
        out[0] = (tc > 0) ? ts / (float)tc : 0.0f;
    }
}

extern "C" void kernel_launch(void* const* d_in, const int* in_sizes, int n_in,
                              void* d_out, int out_size) {
    const float*     X   = (const float*)d_in[0];
    const long long* lab = (const long long*)d_in[1];
    float*           out = (float*)d_out;

    k_labels<<<(BN + 255) / 256, 256>>>(lab);
    k_norm<<<BN, 128>>>(X);
    dim3 grid(BN / 128, BN / 128);
    k_gemm<<<grid, 256>>>();
    k_stats<<<BN, 256>>>();
    k_final<<<1, 256>>>(out);
}

// round 13
// speedup vs baseline: 8.4249x; 1.8693x over previous
#include <cuda_runtime.h>
#include <cuda_bf16.h>
#include <math.h>
#include <stdint.h>

#define BN 8192
#define DD 512
#define MARGIN 0.3f
#define INF 3.4e38f

#define SROW 144                    // smem row stride bytes (128B data + 16 pad)
#define TILE_B (128 * SROW)         // 18432 B per matrix tile (128 rows x 64 bf16)
#define STAGE_B (4 * TILE_B)        // Ahi, Alo, Bhi, Blo
#define DYN_SMEM (2 * STAGE_B)      // double buffered = 147456 B

// -------- device scratch --------
__device__ __nv_bfloat16 g_hi[(size_t)BN * DD];   // bf16 high part (8 MB)
__device__ __nv_bfloat16 g_lo[(size_t)BN * DD];   // bf16 low  part (8 MB)
__device__ float g_sq[BN];
__device__ int   g_lab[BN];
__device__ float g_dist[(size_t)BN * BN];         // 256 MB
__device__ float g_rowval[BN];
__device__ int   g_rowcnt[BN];

// ---------------- helpers ----------------
__device__ __forceinline__ uint32_t smem_u32(const void* p) {
    uint32_t a;
    asm("{ .reg .u64 t; cvta.to.shared.u64 t, %1; cvt.u32.u64 %0, t; }" : "=r"(a) : "l"(p));
    return a;
}
__device__ __forceinline__ void cp_async16(uint32_t dst, const void* src) {
    asm volatile("cp.async.cg.shared.global [%0], [%1], 16;" :: "r"(dst), "l"(src) : "memory");
}
#define CP_COMMIT() asm volatile("cp.async.commit_group;" ::: "memory")
#define CP_WAIT1()  asm volatile("cp.async.wait_group 1;" ::: "memory")
#define CP_WAIT0()  asm volatile("cp.async.wait_group 0;" ::: "memory")

__device__ __forceinline__ void ldm_x4(uint32_t* r, uint32_t addr) {
    asm volatile("ldmatrix.sync.aligned.m8n8.x4.shared.b16 {%0,%1,%2,%3}, [%4];"
        : "=r"(r[0]), "=r"(r[1]), "=r"(r[2]), "=r"(r[3]) : "r"(addr));
}
__device__ __forceinline__ void mma16816(float* c, const uint32_t* a, const uint32_t* b) {
    asm volatile(
        "mma.sync.aligned.m16n8k16.row.col.f32.bf16.bf16.f32 "
        "{%0,%1,%2,%3}, {%4,%5,%6,%7}, {%8,%9}, {%0,%1,%2,%3};"
        : "+f"(c[0]), "+f"(c[1]), "+f"(c[2]), "+f"(c[3])
        : "r"(a[0]), "r"(a[1]), "r"(a[2]), "r"(a[3]), "r"(b[0]), "r"(b[1]));
}

// ---------------- labels ----------------
__global__ void k_labels(const long long* __restrict__ lab) {
    int i = blockIdx.x * blockDim.x + threadIdx.x;
    if (i < BN) g_lab[i] = (int)lab[i];
}

// ---------------- normalize + bf16 hi/lo split ----------------
__global__ void k_norm(const float* __restrict__ X) {
    int row = blockIdx.x;
    int t = threadIdx.x;
    const float4* xr = (const float4*)(X + (size_t)row * DD);
    float4 v = xr[t];
    float ss = v.x * v.x + v.y * v.y + v.z * v.z + v.w * v.w;
    #pragma unroll
    for (int off = 16; off > 0; off >>= 1)
        ss += __shfl_xor_sync(0xffffffffu, ss, off);
    __shared__ float ws[4];
    if ((t & 31) == 0) ws[t >> 5] = ss;
    __syncthreads();
    float tot = ws[0] + ws[1] + ws[2] + ws[3];
    float den = fmaxf(sqrtf(tot), 1e-12f);
    float s = 1.0f / den;
    v.x *= s; v.y *= s; v.z *= s; v.w *= s;

    float f[4] = {v.x, v.y, v.z, v.w};
    __nv_bfloat16 h[4], l[4];
    #pragma unroll
    for (int q = 0; q < 4; q++) {
        h[q] = __float2bfloat16(f[q]);
        l[q] = __float2bfloat16(f[q] - __bfloat162float(h[q]));
    }
    __nv_bfloat162* hp = (__nv_bfloat162*)(g_hi + (size_t)row * DD);
    __nv_bfloat162* lp = (__nv_bfloat162*)(g_lo + (size_t)row * DD);
    hp[2 * t]     = __halves2bfloat162(h[0], h[1]);
    hp[2 * t + 1] = __halves2bfloat162(h[2], h[3]);
    lp[2 * t]     = __halves2bfloat162(l[0], l[1]);
    lp[2 * t + 1] = __halves2bfloat162(l[2], l[3]);
    if (t == 0) g_sq[row] = tot * s * s;
}

// ---------------- HMMA pairwise-distance tile kernel ----------------
// Upper-triangle tiles. D = Ahi·Bhi^T + Ahi·Blo^T + Alo·Bhi^T, f32 accum in regs.
// 128x128 tile, 8 warps (warp tile 32x64), BK=64, cp.async double buffering.
extern __shared__ char dsm[];
__global__ __launch_bounds__(256) void k_gemm_mma() {
    int bi = blockIdx.y;
    int bj = blockIdx.x;
    if (bj < bi) return;

    int tid = threadIdx.x;
    int wid = tid >> 5;
    int lid = tid & 31;
    int row0 = bi * 128;
    int col0 = bj * 128;
    int wm = (wid & 3) * 32;      // warp m offset
    int wn = (wid >> 2) * 64;     // warp n offset

    __shared__ float s_sqr[128], s_sqc[128];
    if (tid < 128) {
        s_sqr[tid] = g_sq[row0 + tid];
        s_sqc[tid] = g_sq[col0 + tid];
    }

    uint32_t sb = smem_u32(dsm);

    const __nv_bfloat16* bases[4];
    bases[0] = g_hi + (size_t)row0 * DD;
    bases[1] = g_lo + (size_t)row0 * DD;
    bases[2] = g_hi + (size_t)col0 * DD;
    bases[3] = g_lo + (size_t)col0 * DD;

    // issue one stage of cp.asyncs: 4 matrices x 128 rows x 8 16B-chunks
    auto issue_stage = [&](int kt, int buf) {
        uint32_t dst0 = sb + buf * STAGE_B;
        #pragma unroll
        for (int i = 0; i < 16; i++) {
            int idx = tid + i * 256;
            int mtx = idx >> 10;
            int rem = idx & 1023;
            int r = rem >> 3;
            int e = rem & 7;
            const void* src = bases[mtx] + (size_t)r * DD + kt * 64 + e * 8;
            cp_async16(dst0 + mtx * TILE_B + r * SROW + e * 16, src);
        }
        CP_COMMIT();
    };

    float acc[2][8][4];
    #pragma unroll
    for (int mt = 0; mt < 2; mt++)
        #pragma unroll
        for (int nt = 0; nt < 8; nt++)
            #pragma unroll
            for (int q = 0; q < 4; q++) acc[mt][nt][q] = 0.0f;

    // lane components for ldmatrix addressing
    int a_r = lid & 15;                      // + m_base
    int a_c = (lid >> 4) * 8;                // + k
    int b_r = (lid & 7) + ((lid & 16) >> 1); // + n_base
    int b_c = (lid & 8);                     // + k

    issue_stage(0, 0);

    for (int kt = 0; kt < 8; kt++) {
        int cur = kt & 1;
        if (kt + 1 < 8) { issue_stage(kt + 1, cur ^ 1); CP_WAIT1(); }
        else            { CP_WAIT0(); }
        __syncthreads();

        uint32_t base = sb + cur * STAGE_B;
        uint32_t aHi = base + 0 * TILE_B;
        uint32_t aLo = base + 1 * TILE_B;
        uint32_t bHi = base + 2 * TILE_B;
        uint32_t bLo = base + 3 * TILE_B;

        #pragma unroll
        for (int ks = 0; ks < 4; ks++) {
            int kcol = ks * 16;
            uint32_t ahi[2][4], alo[2][4];
            #pragma unroll
            for (int mt = 0; mt < 2; mt++) {
                uint32_t off = (uint32_t)(wm + mt * 16 + a_r) * SROW + (kcol + a_c) * 2;
                ldm_x4(ahi[mt], aHi + off);
                ldm_x4(alo[mt], aLo + off);
            }
            #pragma unroll
            for (int ntp = 0; ntp < 4; ntp++) {
                uint32_t offb = (uint32_t)(wn + ntp * 16 + b_r) * SROW + (kcol + b_c) * 2;
                uint32_t bh[4], bl[4];
                ldm_x4(bh, bHi + offb);
                ldm_x4(bl, bLo + offb);
                #pragma unroll
                for (int mt = 0; mt < 2; mt++) {
                    #pragma unroll
                    for (int s = 0; s < 2; s++) {
                        float* c = acc[mt][2 * ntp + s];
                        mma16816(c, ahi[mt], bh + 2 * s);
                        mma16816(c, ahi[mt], bl + 2 * s);
                        mma16816(c, alo[mt], bh + 2 * s);
                    }
                }
            }
        }
        __syncthreads();   // all reads of this stage done before overwrite
    }

    // ---- epilogue: distances into smem Dt (reuses stage buffers) ----
    float* Dt = (float*)dsm;   // 128 x 132 floats = 67.6 KB < DYN_SMEM
    int g  = lid >> 2;
    int t4 = lid & 3;
    #pragma unroll
    for (int mt = 0; mt < 2; mt++) {
        #pragma unroll
        for (int nt = 0; nt < 8; nt++) {
            int rr = wm + mt * 16 + g;
            int cc = wn + nt * 8 + t4 * 2;
            float* c = acc[mt][nt];
            float d2;
            d2 = s_sqr[rr]     + s_sqc[cc]     - 2.0f * c[0];
            Dt[rr * 132 + cc]           = sqrtf(fmaxf(d2, 0.0f));
            d2 = s_sqr[rr]     + s_sqc[cc + 1] - 2.0f * c[1];
            Dt[rr * 132 + cc + 1]       = sqrtf(fmaxf(d2, 0.0f));
            d2 = s_sqr[rr + 8] + s_sqc[cc]     - 2.0f * c[2];
            Dt[(rr + 8) * 132 + cc]     = sqrtf(fmaxf(d2, 0.0f));
            d2 = s_sqr[rr + 8] + s_sqc[cc + 1] - 2.0f * c[3];
            Dt[(rr + 8) * 132 + cc + 1] = sqrtf(fmaxf(d2, 0.0f));
        }
    }
    __syncthreads();

    // direct store (coalesced): thread -> row tid>>1, half tid&1
    {
        int row = tid >> 1, half = tid & 1;
        const float* srcp = Dt + row * 132 + half * 64;
        float4* dstp = (float4*)(g_dist + (size_t)(row0 + row) * BN + col0 + half * 64);
        #pragma unroll
        for (int q = 0; q < 16; q++)
            dstp[q] = make_float4(srcp[q*4], srcp[q*4+1], srcp[q*4+2], srcp[q*4+3]);
    }
    // transposed store: thread -> column cc = tid>>1, half tid&1
    {
        int cc = tid >> 1, half = tid & 1;
        float* dstp = g_dist + (size_t)(col0 + cc) * BN + row0 + half * 64;
        #pragma unroll
        for (int q = 0; q < 16; q++) {
            float4 v;
            v.x = Dt[(half * 64 + q * 4 + 0) * 132 + cc];
            v.y = Dt[(half * 64 + q * 4 + 1) * 132 + cc];
            v.z = Dt[(half * 64 + q * 4 + 2) * 132 + cc];
            v.w = Dt[(half * 64 + q * 4 + 3) * 132 + cc];
            *(float4*)(dstp + q * 4) = v;
        }
    }
}

// ---------------- per-anchor semi-hard stats (unchanged) ----------------
__global__ __launch_bounds__(256) void k_stats() {
    int i = blockIdx.x;
    int tid = threadIdx.x;
    const float* drow = g_dist + (size_t)i * BN;
    int li = g_lab[i];

    float d[32];
    unsigned match = 0;
    float psum = 0.0f;
    int   pcnt = 0;

    #pragma unroll
    for (int c = 0; c < 32; c++) {
        int j = tid + (c << 8);
        float dv = (j == i) ? 0.0f : drow[j];
        d[c] = dv;
        int lj = g_lab[j];
        if (lj == li) { match |= (1u << c); psum += dv; pcnt += 1; }
    }
    #pragma unroll
    for (int off = 16; off > 0; off >>= 1) {
        psum += __shfl_xor_sync(0xffffffffu, psum, off);
        pcnt += __shfl_xor_sync(0xffffffffu, pcnt, off);
    }
    __shared__ float ws[8];
    __shared__ int   wc[8];
    __shared__ float s_mean;
    __shared__ int   s_pcnt;
    int warp = tid >> 5;
    if ((tid & 31) == 0) { ws[warp] = psum; wc[warp] = pcnt; }
    __syncthreads();
    if (tid == 0) {
        float ts = 0.0f; int tc = 0;
        #pragma unroll
        for (int w = 0; w < 8; w++) { ts += ws[w]; tc += wc[w]; }
        s_pcnt = tc;
        s_mean = ts / (float)tc;
    }
    __syncthreads();
    float mean = s_mean;
    int   pc   = s_pcnt;

    float mn = INF;
    #pragma unroll
    for (int c = 0; c < 32; c++) {
        bool neg = ((match >> c) & 1u) == 0u;
        if (neg && d[c] > mean) mn = fminf(mn, d[c]);
    }
    #pragma unroll
    for (int off = 16; off > 0; off >>= 1)
        mn = fminf(mn, __shfl_xor_sync(0xffffffffu, mn, off));
    if ((tid & 31) == 0) ws[warp] = mn;
    __syncthreads();
    if (tid == 0) {
        float mm = INF;
        #pragma unroll
        for (int w = 0; w < 8; w++) mm = fminf(mm, ws[w]);
        bool valid  = (pc > 1) && (pc < BN);
        bool has_sh = (mm < 1e37f);
        bool contrib = valid && has_sh;
        float per = fmaxf(mean - mm + MARGIN, 0.0f);
        g_rowval[i] = contrib ? per : 0.0f;
        g_rowcnt[i] = contrib ? 1 : 0;
    }
}

// ---------------- deterministic final reduction ----------------
__global__ void k_final(float* __restrict__ out) {
    int t = threadIdx.x;
    float s = 0.0f;
    int   c = 0;
    for (int j = t; j < BN; j += 256) { s += g_rowval[j]; c += g_rowcnt[j]; }
    #pragma unroll
    for (int off = 16; off > 0; off >>= 1) {
        s += __shfl_xor_sync(0xffffffffu, s, off);
        c += __shfl_xor_sync(0xffffffffu, c, off);
    }
    __shared__ float ws[8];
    __shared__ int   wc[8];
    int warp = t >> 5;
    if ((t & 31) == 0) { ws[warp] = s; wc[warp] = c; }
    __syncthreads();
    if (t == 0) {
        float ts = 0.0f; int tc = 0;
        #pragma unroll
        for (int w = 0; w < 8; w++) { ts += ws[w]; tc += wc[w]; }
        out[0] = (tc > 0) ? ts / (float)tc : 0.0f;
    }
}

extern "C" void kernel_launch(void* const* d_in, const int* in_sizes, int n_in,
                              void* d_out, int out_size) {
    const float*     X   = (const float*)d_in[0];
    const long long* lab = (const long long*)d_in[1];
    float*           out = (float*)d_out;

    static int s_attr_done = 0;
    if (!s_attr_done) {
        cudaFuncSetAttribute(k_gemm_mma,
                             cudaFuncAttributeMaxDynamicSharedMemorySize, DYN_SMEM);
        s_attr_done = 1;
    }

    k_labels<<<(BN + 255) / 256, 256>>>(lab);
    k_norm<<<BN, 128>>>(X);
    dim3 grid(BN / 128, BN / 128);
    k_gemm_mma<<<grid, 256, DYN_SMEM>>>();
    k_stats<<<BN, 256>>>();
    k_final<<<1, 256>>>(out);
}